// round 3
// baseline (speedup 1.0000x reference)
#include <cuda_runtime.h>
#include <math.h>

#define BB 2
#define TT 2048
#define DD 1024
#define NHH 16
#define HDD 64
constexpr int BT = BB * TT;          // 4096 rows
constexpr int D3 = 3 * DD;           // 3072

// Scratch (no allocations allowed)
__device__ float g_qkv[BB * TT * D3];   // [B,T,3D]
__device__ float g_y[BB * TT * DD];     // [B,T,D] attention output

// ---------------------------------------------------------------------------
// Tiled SGEMM: C[M,N] = A[M,K] @ B[K,N] + bias[N]
// BM=BN=64, BK=16, 256 threads, 4x4 micro-tile per thread.
// ---------------------------------------------------------------------------
template<int BM, int BN, int BK>
__global__ void gemm_bias(const float* __restrict__ A, const float* __restrict__ Bm,
                          const float* __restrict__ bias, float* __restrict__ C,
                          int M, int N, int K)
{
    __shared__ float As[BM][BK];   // [row][k] — conflict-free f4 store & broadcast read
    __shared__ float Bs[BK][BN];   // [k][col]

    const int tid = threadIdx.x;
    const int tx = tid & 15;       // 0..15 -> n
    const int ty = tid >> 4;       // 0..15 -> m
    const int m0 = blockIdx.y * BM;
    const int n0 = blockIdx.x * BN;

    // load indices
    const int ar = tid >> 2;            // 0..63 A row
    const int ac = (tid & 3) * 4;       // 0,4,8,12 within BK
    const int br = tid >> 4;            // 0..15 B k-row
    const int bc = (tid & 15) * 4;      // col within BN

    float acc[4][4];
    #pragma unroll
    for (int i = 0; i < 4; i++)
        #pragma unroll
        for (int j = 0; j < 4; j++) acc[i][j] = 0.f;

    for (int k0 = 0; k0 < K; k0 += BK) {
        *(float4*)&As[ar][ac] = *(const float4*)&A[(size_t)(m0 + ar) * K + k0 + ac];
        *(float4*)&Bs[br][bc] = *(const float4*)&Bm[(size_t)(k0 + br) * N + n0 + bc];
        __syncthreads();

        #pragma unroll
        for (int k = 0; k < BK; k += 4) {
            float4 b0 = *(const float4*)&Bs[k + 0][tx * 4];
            float4 b1 = *(const float4*)&Bs[k + 1][tx * 4];
            float4 b2 = *(const float4*)&Bs[k + 2][tx * 4];
            float4 b3 = *(const float4*)&Bs[k + 3][tx * 4];
            float rb0[4] = {b0.x, b0.y, b0.z, b0.w};
            float rb1[4] = {b1.x, b1.y, b1.z, b1.w};
            float rb2[4] = {b2.x, b2.y, b2.z, b2.w};
            float rb3[4] = {b3.x, b3.y, b3.z, b3.w};
            #pragma unroll
            for (int i = 0; i < 4; i++) {
                float4 a = *(const float4*)&As[ty * 4 + i][k];
                #pragma unroll
                for (int j = 0; j < 4; j++) {
                    acc[i][j] += a.x * rb0[j];
                    acc[i][j] += a.y * rb1[j];
                    acc[i][j] += a.z * rb2[j];
                    acc[i][j] += a.w * rb3[j];
                }
            }
        }
        __syncthreads();
    }

    #pragma unroll
    for (int i = 0; i < 4; i++) {
        const int m = m0 + ty * 4 + i;
        #pragma unroll
        for (int j = 0; j < 4; j++) {
            const int n = n0 + tx * 4 + j;
            C[(size_t)m * N + n] = acc[i][j] + bias[n];
        }
    }
}

// ---------------------------------------------------------------------------
// Flash attention, fp32, causal. BQ=BKV=64, HD=64.
// 256 threads: 4 threads per q-row (thread owns 16 of 64 output cols).
// ---------------------------------------------------------------------------
constexpr int BQ = 64;
constexpr int BKV = 64;
constexpr int QS_STR = 68;   // padded strides to avoid row-broadcast bank conflicts
constexpr int PS_STR = 68;
constexpr int FLASH_SMEM = (BQ * QS_STR + BKV * HDD + BKV * HDD + BQ * PS_STR) * 4; // 67584 B

__global__ void flash_attn()
{
    extern __shared__ float sm[];
    float* Qs = sm;                          // [BQ][QS_STR]
    float* Ks = Qs + BQ * QS_STR;            // [BKV][HD]
    float* Vs = Ks + BKV * HDD;              // [BKV][HD]
    float* Ps = Vs + BKV * HDD;              // [BQ][PS_STR]

    const int tid = threadIdx.x;
    const int r  = tid >> 2;        // q row within tile, 0..63
    const int cg = tid & 3;
    const int c0 = cg * 16;
    const int q0 = blockIdx.x * BQ;
    const int h  = blockIdx.y;
    const int b  = blockIdx.z;

    const float* qkv_b = g_qkv + (size_t)b * TT * D3;

    // load Q tile
    {
        const float* qp = qkv_b + (size_t)(q0 + r) * D3 + h * HDD;
        #pragma unroll
        for (int j = 0; j < 16; j += 4)
            *(float4*)&Qs[r * QS_STR + c0 + j] = *(const float4*)&qp[c0 + j];
    }

    float o[16];
    #pragma unroll
    for (int i = 0; i < 16; i++) o[i] = 0.f;
    float m_r = -1e30f, l_r = 0.f;

    for (int kv0 = 0; kv0 <= q0; kv0 += BKV) {
        __syncthreads();   // prior P@V reads of Ks/Vs/Ps complete (also covers Q store iter0)
        {
            const float* kp = qkv_b + (size_t)(kv0 + r) * D3 + DD + h * HDD;
            const float* vp = kp + DD;
            #pragma unroll
            for (int j = 0; j < 16; j += 4) {
                *(float4*)&Ks[r * HDD + c0 + j] = *(const float4*)&kp[c0 + j];
                *(float4*)&Vs[r * HDD + c0 + j] = *(const float4*)&vp[c0 + j];
            }
        }
        __syncthreads();

        // S chunk: s[jj] = (Q[r] . K[c0+jj]) * 1/sqrt(HD)
        float s[16];
        const float* qrow = &Qs[r * QS_STR];
        #pragma unroll
        for (int jj = 0; jj < 16; jj++) {
            const float* krow = &Ks[(c0 + jj) * HDD];
            float acc = 0.f;
            #pragma unroll
            for (int d = 0; d < HDD; d += 4) {
                float4 qa = *(const float4*)&qrow[d];
                float4 ka = *(const float4*)&krow[d];
                acc += qa.x * ka.x + qa.y * ka.y + qa.z * ka.z + qa.w * ka.w;
            }
            s[jj] = acc * 0.125f;
        }

        if (kv0 == q0) {   // diagonal block: causal mask
            #pragma unroll
            for (int jj = 0; jj < 16; jj++)
                if (c0 + jj > r) s[jj] = -1e30f;
        }

        // row max across this thread's 16 + the other 3 threads of the row
        float mx = s[0];
        #pragma unroll
        for (int jj = 1; jj < 16; jj++) mx = fmaxf(mx, s[jj]);
        mx = fmaxf(mx, __shfl_xor_sync(0xffffffffu, mx, 1));
        mx = fmaxf(mx, __shfl_xor_sync(0xffffffffu, mx, 2));
        const float m_new = fmaxf(m_r, mx);
        const float alpha = __expf(m_r - m_new);

        float psum = 0.f;
        #pragma unroll
        for (int jj = 0; jj < 16; jj++) {
            float p = __expf(s[jj] - m_new);
            s[jj] = p;
            psum += p;
        }
        psum += __shfl_xor_sync(0xffffffffu, psum, 1);
        psum += __shfl_xor_sync(0xffffffffu, psum, 2);
        l_r = l_r * alpha + psum;
        m_r = m_new;
        #pragma unroll
        for (int i = 0; i < 16; i++) o[i] *= alpha;

        // stash P
        #pragma unroll
        for (int jj = 0; jj < 16; jj += 4) {
            float4 p4 = make_float4(s[jj], s[jj + 1], s[jj + 2], s[jj + 3]);
            *(float4*)&Ps[r * PS_STR + c0 + jj] = p4;
        }
        __syncthreads();

        // O[r][c0..c0+15] += P[r][:] @ V[:][c0..]
        #pragma unroll 4
        for (int j = 0; j < BKV; j++) {
            const float p = Ps[r * PS_STR + j];
            const float* vrow = &Vs[j * HDD + c0];
            #pragma unroll
            for (int cc = 0; cc < 16; cc += 4) {
                float4 v4 = *(const float4*)&vrow[cc];
                o[cc + 0] += p * v4.x;
                o[cc + 1] += p * v4.y;
                o[cc + 2] += p * v4.z;
                o[cc + 3] += p * v4.w;
            }
        }
    }

    const float inv_l = 1.f / l_r;
    float* yp = g_y + (size_t)(b * TT + q0 + r) * DD + h * HDD + c0;
    #pragma unroll
    for (int cc = 0; cc < 16; cc += 4) {
        float4 v = make_float4(o[cc] * inv_l, o[cc + 1] * inv_l,
                               o[cc + 2] * inv_l, o[cc + 3] * inv_l);
        *(float4*)&yp[cc] = v;
    }
}

// ---------------------------------------------------------------------------
extern "C" void kernel_launch(void* const* d_in, const int* in_sizes, int n_in,
                              void* d_out, int out_size)
{
    const float* x     = (const float*)d_in[0];
    const float* Wqkv  = (const float*)d_in[1];
    const float* bqkv  = (const float*)d_in[2];
    const float* Wproj = (const float*)d_in[3];
    const float* bproj = (const float*)d_in[4];
    float* out = (float*)d_out;

    float *qkv_ptr, *y_ptr;
    cudaGetSymbolAddress((void**)&qkv_ptr, g_qkv);
    cudaGetSymbolAddress((void**)&y_ptr, g_y);

    cudaFuncSetAttribute(flash_attn, cudaFuncAttributeMaxDynamicSharedMemorySize, FLASH_SMEM);

    // 1) QKV = x @ Wqkv + bqkv       [4096,1024] @ [1024,3072]
    gemm_bias<64, 64, 16><<<dim3(D3 / 64, BT / 64), 256>>>(x, Wqkv, bqkv, qkv_ptr, BT, D3, DD);

    // 2) causal flash attention -> g_y [B,T,D]
    flash_attn<<<dim3(TT / BQ, NHH, BB), 256, FLASH_SMEM>>>();

    // 3) out = y @ Wproj + bproj     [4096,1024] @ [1024,1024]
    gemm_bias<64, 64, 16><<<dim3(DD / 64, BT / 64), 256>>>(y_ptr, Wproj, bproj, out, BT, DD, DD);
}

// round 5
// speedup vs baseline: 3.4189x; 3.4189x over previous
#include <cuda_runtime.h>
#include <math.h>

#define BB 2
#define TT 2048
#define DD 1024
#define NHH 16
#define HDD 64
constexpr int BT = BB * TT;          // 4096 rows
constexpr int D3 = 3 * DD;           // 3072

// Scratch (no allocations allowed)
__device__ float g_qkv[BB * TT * D3];   // [B,T,3D]
__device__ float g_y[BB * TT * DD];     // [B,T,D]

using u64 = unsigned long long;

// ---- packed fp32x2 helpers (FFMA2 path, PTX-only) ----
__device__ __forceinline__ u64 pk2(float x, float y) {
    u64 r; asm("mov.b64 %0, {%1, %2};" : "=l"(r) : "f"(x), "f"(y)); return r;
}
__device__ __forceinline__ void upk2(u64 v, float& x, float& y) {
    asm("mov.b64 {%0, %1}, %2;" : "=f"(x), "=f"(y) : "l"(v));
}
__device__ __forceinline__ u64 fma2(u64 a, u64 b, u64 c) {
    u64 d; asm("fma.rn.f32x2 %0, %1, %2, %3;" : "=l"(d) : "l"(a), "l"(b), "l"(c)); return d;
}
__device__ __forceinline__ u64 mul2(u64 a, u64 b) {
    u64 d; asm("mul.rn.f32x2 %0, %1, %2;" : "=l"(d) : "l"(a), "l"(b)); return d;
}

// ---------------------------------------------------------------------------
// SGEMM: C[M,N] = A[M,K] @ B[K,N] + bias[N]
// BM=BN=128, BK=16, 256 threads, 8x8 micro-tile, FFMA2, reg-prefetch pipeline.
// A stored k-major (transposed) in smem for f4 fragment loads.
// ---------------------------------------------------------------------------
template<int BM, int BN, int BK>
__global__ __launch_bounds__(256, 2)
void gemm_bias(const float* __restrict__ A, const float* __restrict__ Bm,
               const float* __restrict__ bias, float* __restrict__ C,
               int M, int N, int K)
{
    constexpr int AST = BM + 4;   // 132: conflict-free scalar transpose stores
    constexpr int BST = BN + 4;
    __shared__ float Ast[BK][AST];   // [k][m]
    __shared__ float Bs[BK][BST];    // [k][n]

    const int tid = threadIdx.x;
    const int tx = tid & 15;
    const int ty = tid >> 4;
    const int m0 = blockIdx.y * BM;
    const int n0 = blockIdx.x * BN;

    // A fill: lane-consecutive rows (conflict-free STS), 16 floats/thread
    const int am  = tid & 127;
    const int akc = (tid >> 7) * 4;       // 0 or 4; +8 for second chunk
    // B fill: natural layout
    const int bk = tid >> 5;              // 0..7 ; +8 for second chunk
    const int bc = (tid & 31) * 4;

    const float* Aptr = A + (size_t)(m0 + am) * K + akc;
    const float* Bptr = Bm + (size_t)bk * N + n0 + bc;

    float4 ra0 = *(const float4*)(Aptr);
    float4 ra1 = *(const float4*)(Aptr + 8);
    float4 rb0 = *(const float4*)(Bptr);
    float4 rb1 = *(const float4*)(Bptr + (size_t)8 * N);

    u64 acc[8][4];
    #pragma unroll
    for (int i = 0; i < 8; i++)
        #pragma unroll
        for (int j = 0; j < 4; j++) acc[i][j] = 0ull;   // (0.f,0.f)

    for (int k0 = 0; k0 < K; k0 += BK) {
        Ast[akc + 0][am] = ra0.x;  Ast[akc + 1][am] = ra0.y;
        Ast[akc + 2][am] = ra0.z;  Ast[akc + 3][am] = ra0.w;
        Ast[akc + 8][am] = ra1.x;  Ast[akc + 9][am] = ra1.y;
        Ast[akc + 10][am] = ra1.z; Ast[akc + 11][am] = ra1.w;
        *(float4*)&Bs[bk][bc]     = rb0;
        *(float4*)&Bs[bk + 8][bc] = rb1;
        __syncthreads();

        if (k0 + BK < K) {   // prefetch next tile into regs (overlaps compute)
            ra0 = *(const float4*)(Aptr + k0 + BK);
            ra1 = *(const float4*)(Aptr + k0 + BK + 8);
            rb0 = *(const float4*)(Bptr + (size_t)(k0 + BK) * N);
            rb1 = *(const float4*)(Bptr + (size_t)(k0 + BK + 8) * N);
        }

        #pragma unroll
        for (int k = 0; k < BK; k++) {
            float4 a0 = *(const float4*)&Ast[k][ty * 8];
            float4 a1 = *(const float4*)&Ast[k][ty * 8 + 4];
            float4 b0 = *(const float4*)&Bs[k][tx * 8];
            float4 b1 = *(const float4*)&Bs[k][tx * 8 + 4];
            u64 bp[4] = { pk2(b0.x, b0.y), pk2(b0.z, b0.w),
                          pk2(b1.x, b1.y), pk2(b1.z, b1.w) };
            float av[8] = { a0.x, a0.y, a0.z, a0.w, a1.x, a1.y, a1.z, a1.w };
            #pragma unroll
            for (int i = 0; i < 8; i++) {
                u64 ad = pk2(av[i], av[i]);
                #pragma unroll
                for (int j = 0; j < 4; j++) acc[i][j] = fma2(ad, bp[j], acc[i][j]);
            }
        }
        __syncthreads();
    }

    const float4 bia0 = *(const float4*)&bias[n0 + tx * 8];
    const float4 bia1 = *(const float4*)&bias[n0 + tx * 8 + 4];
    #pragma unroll
    for (int i = 0; i < 8; i++) {
        float v[8];
        #pragma unroll
        for (int j = 0; j < 4; j++) upk2(acc[i][j], v[2 * j], v[2 * j + 1]);
        float4 o0 = make_float4(v[0] + bia0.x, v[1] + bia0.y, v[2] + bia0.z, v[3] + bia0.w);
        float4 o1 = make_float4(v[4] + bia1.x, v[5] + bia1.y, v[6] + bia1.z, v[7] + bia1.w);
        float* cp = C + (size_t)(m0 + ty * 8 + i) * N + n0 + tx * 8;
        *(float4*)cp = o0;
        *(float4*)(cp + 4) = o1;
    }
}

// ---------------------------------------------------------------------------
// Flash attention, fp32 FFMA2, causal. BQ=BKV=64, HD=64.
// 256 threads = 16x16; each thread: 4x4 S-frag (rows 4ty, cols 4tx) and
// 4x4 O-frag (rows 4ty, dims 4tx). Q,K stored d-major in smem; V,P row-major.
// K/V prefetched gmem->regs overlapped with the S phase of the previous tile.
// ---------------------------------------------------------------------------
constexpr int BQ = 64;
constexpr int BKV = 64;
constexpr int ST = 68;                       // padded stride (floats)
constexpr int FLASH_SMEM = 4 * 64 * ST * 4;  // Qt,Kt,Vs,Ps = 69632 B

__global__ __launch_bounds__(256, 2) void flash_attn()
{
    extern __shared__ float sm[];
    float* Qt = sm;                 // [d][qrow]   (q pre-scaled by 1/8)
    float* Kt = Qt + 64 * ST;       // [d][kcol]
    float* Vs = Kt + 64 * ST;       // [kvrow][d]
    float* Ps = Vs + 64 * ST;       // [qrow][kcol]

    const int tid = threadIdx.x;
    const int tx = tid & 15;
    const int ty = tid >> 4;
    const int r0 = ty * 4;
    const int c0 = tx * 4;
    const int q0 = blockIdx.x * BQ;
    const int h  = blockIdx.y;
    const int b  = blockIdx.z;

    const float* qkv_b = g_qkv + (size_t)b * TT * D3;

    // ---- Q fill (transposed, scaled): qr lane-consecutive -> conflict-free STS
    {
        const int qr = tid & 63;
        const int dc = (tid >> 6) * 16;
        const float* qp = qkv_b + (size_t)(q0 + qr) * D3 + h * HDD + dc;
        #pragma unroll
        for (int c = 0; c < 4; c++) {
            float4 q4 = *(const float4*)(qp + 4 * c);
            Qt[(dc + 4 * c + 0) * ST + qr] = q4.x * 0.125f;
            Qt[(dc + 4 * c + 1) * ST + qr] = q4.y * 0.125f;
            Qt[(dc + 4 * c + 2) * ST + qr] = q4.z * 0.125f;
            Qt[(dc + 4 * c + 3) * ST + qr] = q4.w * 0.125f;
        }
    }

    // K/V prefetch mappings
    const int krow = tid & 63;
    const int kdc  = (tid >> 6) * 16;
    const int vrow = tid >> 2;
    const int vdc  = (tid & 3) * 16;
    const float* kbase = qkv_b + (size_t)krow * D3 + DD + h * HDD + kdc;
    const float* vbase = qkv_b + (size_t)vrow * D3 + 2 * DD + h * HDD + vdc;

    float4 rk[4], rv[4];
    #pragma unroll
    for (int c = 0; c < 4; c++) {           // tile 0 prefetch
        rk[c] = *(const float4*)(kbase + 4 * c);
        rv[c] = *(const float4*)(vbase + 4 * c);
    }

    u64 o2[4][2];
    #pragma unroll
    for (int i = 0; i < 4; i++) { o2[i][0] = 0ull; o2[i][1] = 0ull; }
    float m_r[4] = { -1e30f, -1e30f, -1e30f, -1e30f };
    float l_r[4] = { 0.f, 0.f, 0.f, 0.f };

    const int nt = q0 / BKV + 1;
    for (int it = 0; it < nt; it++) {
        __syncthreads();                       // prev PV reads of Vs/Ps done
        #pragma unroll
        for (int c = 0; c < 4; c++) {          // store K transposed, V natural
            Kt[(kdc + 4 * c + 0) * ST + krow] = rk[c].x;
            Kt[(kdc + 4 * c + 1) * ST + krow] = rk[c].y;
            Kt[(kdc + 4 * c + 2) * ST + krow] = rk[c].z;
            Kt[(kdc + 4 * c + 3) * ST + krow] = rk[c].w;
            *(float4*)&Vs[vrow * ST + vdc + 4 * c] = rv[c];
        }
        __syncthreads();

        if (it + 1 < nt) {                     // prefetch next tile (overlaps S)
            const size_t off = (size_t)(it + 1) * BKV * D3;
            #pragma unroll
            for (int c = 0; c < 4; c++) {
                rk[c] = *(const float4*)(kbase + off + 4 * c);
                rv[c] = *(const float4*)(vbase + off + 4 * c);
            }
        }

        // ---- S = Q @ K^T (outer product over d)
        u64 s2[4][2];
        #pragma unroll
        for (int i = 0; i < 4; i++) { s2[i][0] = 0ull; s2[i][1] = 0ull; }
        #pragma unroll 8
        for (int d = 0; d < HDD; d++) {
            float4 q4 = *(const float4*)&Qt[d * ST + r0];
            float4 k4 = *(const float4*)&Kt[d * ST + c0];
            u64 kp0 = pk2(k4.x, k4.y), kp1 = pk2(k4.z, k4.w);
            float qv[4] = { q4.x, q4.y, q4.z, q4.w };
            #pragma unroll
            for (int i = 0; i < 4; i++) {
                u64 qd = pk2(qv[i], qv[i]);
                s2[i][0] = fma2(qd, kp0, s2[i][0]);
                s2[i][1] = fma2(qd, kp1, s2[i][1]);
            }
        }

        float s[4][4];
        #pragma unroll
        for (int i = 0; i < 4; i++) {
            upk2(s2[i][0], s[i][0], s[i][1]);
            upk2(s2[i][1], s[i][2], s[i][3]);
        }

        if (it == nt - 1) {                    // diagonal tile: causal mask
            #pragma unroll
            for (int i = 0; i < 4; i++)
                #pragma unroll
                for (int j = 0; j < 4; j++)
                    if (c0 + j > r0 + i) s[i][j] = -1e30f;
        }

        // ---- online softmax (row groups = 16 contiguous lanes)
        #pragma unroll
        for (int i = 0; i < 4; i++) {
            float mx = fmaxf(fmaxf(s[i][0], s[i][1]), fmaxf(s[i][2], s[i][3]));
            mx = fmaxf(mx, __shfl_xor_sync(0xffffffffu, mx, 1));
            mx = fmaxf(mx, __shfl_xor_sync(0xffffffffu, mx, 2));
            mx = fmaxf(mx, __shfl_xor_sync(0xffffffffu, mx, 4));
            mx = fmaxf(mx, __shfl_xor_sync(0xffffffffu, mx, 8));
            const float m_new = fmaxf(m_r[i], mx);
            const float alpha = __expf(m_r[i] - m_new);
            float ps = 0.f;
            #pragma unroll
            for (int j = 0; j < 4; j++) {
                s[i][j] = __expf(s[i][j] - m_new);
                ps += s[i][j];
            }
            ps += __shfl_xor_sync(0xffffffffu, ps, 1);
            ps += __shfl_xor_sync(0xffffffffu, ps, 2);
            ps += __shfl_xor_sync(0xffffffffu, ps, 4);
            ps += __shfl_xor_sync(0xffffffffu, ps, 8);
            l_r[i] = l_r[i] * alpha + ps;
            m_r[i] = m_new;
            u64 ad = pk2(alpha, alpha);
            o2[i][0] = mul2(o2[i][0], ad);
            o2[i][1] = mul2(o2[i][1], ad);
            *(float4*)&Ps[(r0 + i) * ST + c0] =
                make_float4(s[i][0], s[i][1], s[i][2], s[i][3]);
        }
        __syncthreads();

        // ---- O += P @ V (outer product over kv col c)
        #pragma unroll 8
        for (int c = 0; c < BKV; c++) {
            float4 v4 = *(const float4*)&Vs[c * ST + c0];   // d0 == c0
            u64 vp0 = pk2(v4.x, v4.y), vp1 = pk2(v4.z, v4.w);
            #pragma unroll
            for (int i = 0; i < 4; i++) {
                float p = Ps[(r0 + i) * ST + c];
                u64 pd = pk2(p, p);
                o2[i][0] = fma2(pd, vp0, o2[i][0]);
                o2[i][1] = fma2(pd, vp1, o2[i][1]);
            }
        }
    }

    #pragma unroll
    for (int i = 0; i < 4; i++) {
        const float inv_l = 1.f / l_r[i];
        float v[4];
        upk2(o2[i][0], v[0], v[1]);
        upk2(o2[i][1], v[2], v[3]);
        float* yp = g_y + (size_t)(b * TT + q0 + r0 + i) * DD + h * HDD + c0;
        *(float4*)yp = make_float4(v[0] * inv_l, v[1] * inv_l,
                                   v[2] * inv_l, v[3] * inv_l);
    }
}

// ---------------------------------------------------------------------------
extern "C" void kernel_launch(void* const* d_in, const int* in_sizes, int n_in,
                              void* d_out, int out_size)
{
    const float* x     = (const float*)d_in[0];
    const float* Wqkv  = (const float*)d_in[1];
    const float* bqkv  = (const float*)d_in[2];
    const float* Wproj = (const float*)d_in[3];
    const float* bproj = (const float*)d_in[4];
    float* out = (float*)d_out;

    float *qkv_ptr, *y_ptr;
    cudaGetSymbolAddress((void**)&qkv_ptr, g_qkv);
    cudaGetSymbolAddress((void**)&y_ptr, g_y);

    cudaFuncSetAttribute(flash_attn, cudaFuncAttributeMaxDynamicSharedMemorySize, FLASH_SMEM);

    // 1) QKV = x @ Wqkv + bqkv       [4096,1024] @ [1024,3072]
    gemm_bias<128, 128, 16><<<dim3(D3 / 128, BT / 128), 256>>>(x, Wqkv, bqkv, qkv_ptr, BT, D3, DD);

    // 2) causal flash attention -> g_y [B,T,D]
    flash_attn<<<dim3(TT / BQ, NHH, BB), 256, FLASH_SMEM>>>();

    // 3) out = y @ Wproj + bproj     [4096,1024] @ [1024,1024]
    gemm_bias<128, 128, 16><<<dim3(DD / 128, BT / 128), 256>>>(y_ptr, Wproj, bproj, out, BT, DD, DD);
}

// round 8
// speedup vs baseline: 4.7417x; 1.3869x over previous
#include <cuda_runtime.h>
#include <math.h>
#include <stdint.h>

#define BB 2
#define TT 2048
#define DD 1024
#define NHH 16
#define HDD 64
constexpr int BT = BB * TT;          // 4096 rows
constexpr int D3 = 3 * DD;           // 3072

// Scratch (no allocations allowed)
__device__ float g_qkv[BB * TT * D3];   // [B,T,3D]
__device__ float g_y[BB * TT * DD];     // [B,T,D]

using u64 = unsigned long long;

// ---- packed fp32x2 helpers (FFMA2 path, PTX-only) ----
__device__ __forceinline__ u64 pk2(float x, float y) {
    u64 r; asm("mov.b64 %0, {%1, %2};" : "=l"(r) : "f"(x), "f"(y)); return r;
}
__device__ __forceinline__ void upk2(u64 v, float& x, float& y) {
    asm("mov.b64 {%0, %1}, %2;" : "=f"(x), "=f"(y) : "l"(v));
}
__device__ __forceinline__ u64 fma2(u64 a, u64 b, u64 c) {
    u64 d; asm("fma.rn.f32x2 %0, %1, %2, %3;" : "=l"(d) : "l"(a), "l"(b), "l"(c)); return d;
}
__device__ __forceinline__ u64 mul2(u64 a, u64 b) {
    u64 d; asm("mul.rn.f32x2 %0, %1, %2;" : "=l"(d) : "l"(a), "l"(b)); return d;
}

// ---- tf32 helpers ----
__device__ __forceinline__ uint32_t f2tf32(float f) {
    uint32_t r; asm("cvt.rna.tf32.f32 %0, %1;" : "=r"(r) : "f"(f)); return r;
}
__device__ __forceinline__ void mma_tf32(float& d0, float& d1, float& d2, float& d3,
                                         uint32_t a0, uint32_t a1, uint32_t a2, uint32_t a3,
                                         uint32_t b0, uint32_t b1) {
    asm("mma.sync.aligned.m16n8k8.row.col.f32.tf32.tf32.f32 "
        "{%0,%1,%2,%3}, {%4,%5,%6,%7}, {%8,%9}, {%0,%1,%2,%3};"
        : "+f"(d0), "+f"(d1), "+f"(d2), "+f"(d3)
        : "r"(a0), "r"(a1), "r"(a2), "r"(a3), "r"(b0), "r"(b1));
}

// ---------------------------------------------------------------------------
// tf32 tensor-core GEMM: C[M,N] = A[M,K] @ B[K,N] + bias[N]
// BM=BN=128, BK=16, 256 threads (8 warps, 2x4 warp grid, 64x32 warp tile).
// m16n8k8 tf32 mma; A/B in smem k-major [16][136] (conflict-free frag LDS).
// ---------------------------------------------------------------------------
constexpr int GBK = 16;
constexpr int GPAD = 136;   // 136%32=8 -> k-strided frag loads hit disjoint bank sets

__global__ __launch_bounds__(256, 2)
void gemm_tf32(const float* __restrict__ A, const float* __restrict__ Bm,
               const float* __restrict__ bias, float* __restrict__ C,
               int M, int N, int K)
{
    __shared__ uint32_t As[GBK][GPAD];   // [k][m]  (tf32 bits)
    __shared__ uint32_t Bs[GBK][GPAD];   // [k][n]

    const int tid  = threadIdx.x;
    const int lane = tid & 31;
    const int wid  = tid >> 5;
    const int wm   = (wid >> 2) * 64;    // warp m offset (0 or 64)
    const int wn   = (wid & 3) * 32;     // warp n offset
    const int m0 = blockIdx.y * 128;
    const int n0 = blockIdx.x * 128;

    // A fill: row am = tid&127 (lane-consecutive -> conflict-free transpose STS)
    const int am  = tid & 127;
    const int akc = (tid >> 7) * 4;          // 0 or 4 ; +8 for second chunk
    // B fill: natural layout
    const int bk = tid >> 5;                 // 0..7 ; +8 second chunk
    const int bc = (tid & 31) * 4;

    const float* Aptr = A + (size_t)(m0 + am) * K + akc;
    const float* Bptr = Bm + (size_t)bk * N + n0 + bc;

    float4 ra0 = *(const float4*)(Aptr);
    float4 ra1 = *(const float4*)(Aptr + 8);
    float4 rb0 = *(const float4*)(Bptr);
    float4 rb1 = *(const float4*)(Bptr + (size_t)8 * N);

    float acc[4][4][4];
    #pragma unroll
    for (int i = 0; i < 4; i++)
        #pragma unroll
        for (int j = 0; j < 4; j++)
            #pragma unroll
            for (int t = 0; t < 4; t++) acc[i][j][t] = 0.f;

    const int kq = lane & 3;       // k within quad
    const int gq = lane >> 2;      // group id 0..7

    for (int k0 = 0; k0 < K; k0 += GBK) {
        As[akc + 0][am] = f2tf32(ra0.x);  As[akc + 1][am] = f2tf32(ra0.y);
        As[akc + 2][am] = f2tf32(ra0.z);  As[akc + 3][am] = f2tf32(ra0.w);
        As[akc + 8][am] = f2tf32(ra1.x);  As[akc + 9][am] = f2tf32(ra1.y);
        As[akc + 10][am] = f2tf32(ra1.z); As[akc + 11][am] = f2tf32(ra1.w);
        {
            uint4 q0 = make_uint4(f2tf32(rb0.x), f2tf32(rb0.y), f2tf32(rb0.z), f2tf32(rb0.w));
            uint4 q1 = make_uint4(f2tf32(rb1.x), f2tf32(rb1.y), f2tf32(rb1.z), f2tf32(rb1.w));
            *(uint4*)&Bs[bk][bc]     = q0;
            *(uint4*)&Bs[bk + 8][bc] = q1;
        }
        __syncthreads();

        if (k0 + GBK < K) {   // prefetch next tile into regs
            ra0 = *(const float4*)(Aptr + k0 + GBK);
            ra1 = *(const float4*)(Aptr + k0 + GBK + 8);
            rb0 = *(const float4*)(Bptr + (size_t)(k0 + GBK) * N);
            rb1 = *(const float4*)(Bptr + (size_t)(k0 + GBK + 8) * N);
        }

        #pragma unroll
        for (int ks = 0; ks < GBK; ks += 8) {
            const int kk = ks + kq;
            uint32_t af[4][4], bf[4][2];
            #pragma unroll
            for (int i = 0; i < 4; i++) {
                const int mi = wm + i * 16 + gq;
                af[i][0] = As[kk][mi];
                af[i][1] = As[kk][mi + 8];
                af[i][2] = As[kk + 4][mi];
                af[i][3] = As[kk + 4][mi + 8];
            }
            #pragma unroll
            for (int j = 0; j < 4; j++) {
                const int nj = wn + j * 8 + gq;
                bf[j][0] = Bs[kk][nj];
                bf[j][1] = Bs[kk + 4][nj];
            }
            #pragma unroll
            for (int i = 0; i < 4; i++)
                #pragma unroll
                for (int j = 0; j < 4; j++)
                    mma_tf32(acc[i][j][0], acc[i][j][1], acc[i][j][2], acc[i][j][3],
                             af[i][0], af[i][1], af[i][2], af[i][3],
                             bf[j][0], bf[j][1]);
        }
        __syncthreads();
    }

    // epilogue: d0,d1 -> (row, col), (row, col+1); d2,d3 -> row+8
    #pragma unroll
    for (int j = 0; j < 4; j++) {
        const int col = n0 + wn + j * 8 + 2 * kq;
        const float bi0 = bias[col];
        const float bi1 = bias[col + 1];
        #pragma unroll
        for (int i = 0; i < 4; i++) {
            const int row = m0 + wm + i * 16 + gq;
            float2 v0 = make_float2(acc[i][j][0] + bi0, acc[i][j][1] + bi1);
            float2 v1 = make_float2(acc[i][j][2] + bi0, acc[i][j][3] + bi1);
            *(float2*)&C[(size_t)row * N + col]       = v0;
            *(float2*)&C[(size_t)(row + 8) * N + col] = v1;
        }
    }
}

// ---------------------------------------------------------------------------
// Flash attention, fp32 FFMA2, causal. BQ=BKV=64, HD=64. (unchanged from R4)
// ---------------------------------------------------------------------------
constexpr int BQ = 64;
constexpr int BKV = 64;
constexpr int ST = 68;
constexpr int FLASH_SMEM = 4 * 64 * ST * 4;  // 69632 B

__global__ __launch_bounds__(256, 2) void flash_attn()
{
    extern __shared__ float sm[];
    float* Qt = sm;                 // [d][qrow]   (q pre-scaled by 1/8)
    float* Kt = Qt + 64 * ST;       // [d][kcol]
    float* Vs = Kt + 64 * ST;       // [kvrow][d]
    float* Ps = Vs + 64 * ST;       // [qrow][kcol]

    const int tid = threadIdx.x;
    const int tx = tid & 15;
    const int ty = tid >> 4;
    const int r0 = ty * 4;
    const int c0 = tx * 4;
    const int q0 = blockIdx.x * BQ;
    const int h  = blockIdx.y;
    const int b  = blockIdx.z;

    const float* qkv_b = g_qkv + (size_t)b * TT * D3;

    {
        const int qr = tid & 63;
        const int dc = (tid >> 6) * 16;
        const float* qp = qkv_b + (size_t)(q0 + qr) * D3 + h * HDD + dc;
        #pragma unroll
        for (int c = 0; c < 4; c++) {
            float4 q4 = *(const float4*)(qp + 4 * c);
            Qt[(dc + 4 * c + 0) * ST + qr] = q4.x * 0.125f;
            Qt[(dc + 4 * c + 1) * ST + qr] = q4.y * 0.125f;
            Qt[(dc + 4 * c + 2) * ST + qr] = q4.z * 0.125f;
            Qt[(dc + 4 * c + 3) * ST + qr] = q4.w * 0.125f;
        }
    }

    const int krow = tid & 63;
    const int kdc  = (tid >> 6) * 16;
    const int vrow = tid >> 2;
    const int vdc  = (tid & 3) * 16;
    const float* kbase = qkv_b + (size_t)krow * D3 + DD + h * HDD + kdc;
    const float* vbase = qkv_b + (size_t)vrow * D3 + 2 * DD + h * HDD + vdc;

    float4 rk[4], rv[4];
    #pragma unroll
    for (int c = 0; c < 4; c++) {
        rk[c] = *(const float4*)(kbase + 4 * c);
        rv[c] = *(const float4*)(vbase + 4 * c);
    }

    u64 o2[4][2];
    #pragma unroll
    for (int i = 0; i < 4; i++) { o2[i][0] = 0ull; o2[i][1] = 0ull; }
    float m_r[4] = { -1e30f, -1e30f, -1e30f, -1e30f };
    float l_r[4] = { 0.f, 0.f, 0.f, 0.f };

    const int nt = q0 / BKV + 1;
    for (int it = 0; it < nt; it++) {
        __syncthreads();
        #pragma unroll
        for (int c = 0; c < 4; c++) {
            Kt[(kdc + 4 * c + 0) * ST + krow] = rk[c].x;
            Kt[(kdc + 4 * c + 1) * ST + krow] = rk[c].y;
            Kt[(kdc + 4 * c + 2) * ST + krow] = rk[c].z;
            Kt[(kdc + 4 * c + 3) * ST + krow] = rk[c].w;
            *(float4*)&Vs[vrow * ST + vdc + 4 * c] = rv[c];
        }
        __syncthreads();

        if (it + 1 < nt) {
            const size_t off = (size_t)(it + 1) * BKV * D3;
            #pragma unroll
            for (int c = 0; c < 4; c++) {
                rk[c] = *(const float4*)(kbase + off + 4 * c);
                rv[c] = *(const float4*)(vbase + off + 4 * c);
            }
        }

        u64 s2[4][2];
        #pragma unroll
        for (int i = 0; i < 4; i++) { s2[i][0] = 0ull; s2[i][1] = 0ull; }
        #pragma unroll 8
        for (int d = 0; d < HDD; d++) {
            float4 q4 = *(const float4*)&Qt[d * ST + r0];
            float4 k4 = *(const float4*)&Kt[d * ST + c0];
            u64 kp0 = pk2(k4.x, k4.y), kp1 = pk2(k4.z, k4.w);
            float qv[4] = { q4.x, q4.y, q4.z, q4.w };
            #pragma unroll
            for (int i = 0; i < 4; i++) {
                u64 qd = pk2(qv[i], qv[i]);
                s2[i][0] = fma2(qd, kp0, s2[i][0]);
                s2[i][1] = fma2(qd, kp1, s2[i][1]);
            }
        }

        float s[4][4];
        #pragma unroll
        for (int i = 0; i < 4; i++) {
            upk2(s2[i][0], s[i][0], s[i][1]);
            upk2(s2[i][1], s[i][2], s[i][3]);
        }

        if (it == nt - 1) {
            #pragma unroll
            for (int i = 0; i < 4; i++)
                #pragma unroll
                for (int j = 0; j < 4; j++)
                    if (c0 + j > r0 + i) s[i][j] = -1e30f;
        }

        #pragma unroll
        for (int i = 0; i < 4; i++) {
            float mx = fmaxf(fmaxf(s[i][0], s[i][1]), fmaxf(s[i][2], s[i][3]));
            mx = fmaxf(mx, __shfl_xor_sync(0xffffffffu, mx, 1));
            mx = fmaxf(mx, __shfl_xor_sync(0xffffffffu, mx, 2));
            mx = fmaxf(mx, __shfl_xor_sync(0xffffffffu, mx, 4));
            mx = fmaxf(mx, __shfl_xor_sync(0xffffffffu, mx, 8));
            const float m_new = fmaxf(m_r[i], mx);
            const float alpha = __expf(m_r[i] - m_new);
            float ps = 0.f;
            #pragma unroll
            for (int j = 0; j < 4; j++) {
                s[i][j] = __expf(s[i][j] - m_new);
                ps += s[i][j];
            }
            ps += __shfl_xor_sync(0xffffffffu, ps, 1);
            ps += __shfl_xor_sync(0xffffffffu, ps, 2);
            ps += __shfl_xor_sync(0xffffffffu, ps, 4);
            ps += __shfl_xor_sync(0xffffffffu, ps, 8);
            l_r[i] = l_r[i] * alpha + ps;
            m_r[i] = m_new;
            u64 ad = pk2(alpha, alpha);
            o2[i][0] = mul2(o2[i][0], ad);
            o2[i][1] = mul2(o2[i][1], ad);
            *(float4*)&Ps[(r0 + i) * ST + c0] =
                make_float4(s[i][0], s[i][1], s[i][2], s[i][3]);
        }
        __syncthreads();

        #pragma unroll 8
        for (int c = 0; c < BKV; c++) {
            float4 v4 = *(const float4*)&Vs[c * ST + c0];
            u64 vp0 = pk2(v4.x, v4.y), vp1 = pk2(v4.z, v4.w);
            #pragma unroll
            for (int i = 0; i < 4; i++) {
                float p = Ps[(r0 + i) * ST + c];
                u64 pd = pk2(p, p);
                o2[i][0] = fma2(pd, vp0, o2[i][0]);
                o2[i][1] = fma2(pd, vp1, o2[i][1]);
            }
        }
    }

    #pragma unroll
    for (int i = 0; i < 4; i++) {
        const float inv_l = 1.f / l_r[i];
        float v[4];
        upk2(o2[i][0], v[0], v[1]);
        upk2(o2[i][1], v[2], v[3]);
        float* yp = g_y + (size_t)(b * TT + q0 + r0 + i) * DD + h * HDD + c0;
        *(float4*)yp = make_float4(v[0] * inv_l, v[1] * inv_l,
                                   v[2] * inv_l, v[3] * inv_l);
    }
}

// ---------------------------------------------------------------------------
extern "C" void kernel_launch(void* const* d_in, const int* in_sizes, int n_in,
                              void* d_out, int out_size)
{
    const float* x     = (const float*)d_in[0];
    const float* Wqkv  = (const float*)d_in[1];
    const float* bqkv  = (const float*)d_in[2];
    const float* Wproj = (const float*)d_in[3];
    const float* bproj = (const float*)d_in[4];
    float* out = (float*)d_out;

    float *qkv_ptr, *y_ptr;
    cudaGetSymbolAddress((void**)&qkv_ptr, g_qkv);
    cudaGetSymbolAddress((void**)&y_ptr, g_y);

    cudaFuncSetAttribute(flash_attn, cudaFuncAttributeMaxDynamicSharedMemorySize, FLASH_SMEM);

    // 1) QKV = x @ Wqkv + bqkv       [4096,1024] @ [1024,3072]
    gemm_tf32<<<dim3(D3 / 128, BT / 128), 256>>>(x, Wqkv, bqkv, qkv_ptr, BT, D3, DD);

    // 2) causal flash attention -> g_y [B,T,D]
    flash_attn<<<dim3(TT / BQ, NHH, BB), 256, FLASH_SMEM>>>();

    // 3) out = y @ Wproj + bproj     [4096,1024] @ [1024,1024]
    gemm_tf32<<<dim3(DD / 128, BT / 128), 256>>>(y_ptr, Wproj, bproj, out, BT, DD, DD);
}

// round 9
// speedup vs baseline: 4.7876x; 1.0097x over previous
#include <cuda_runtime.h>
#include <math.h>
#include <stdint.h>

#define BB 2
#define TT 2048
#define DD 1024
#define NHH 16
#define HDD 64
constexpr int BT = BB * TT;          // 4096 rows
constexpr int D3 = 3 * DD;           // 3072

// Scratch (no allocations allowed)
__device__ float g_qkv[BB * TT * D3];   // [B,T,3D]
__device__ float g_y[BB * TT * DD];     // [B,T,D]

// ---- tf32 helpers ----
__device__ __forceinline__ uint32_t f2tf32(float f) {
    uint32_t r; asm("cvt.rna.tf32.f32 %0, %1;" : "=r"(r) : "f"(f)); return r;
}
__device__ __forceinline__ void mma_tf32(float& d0, float& d1, float& d2, float& d3,
                                         uint32_t a0, uint32_t a1, uint32_t a2, uint32_t a3,
                                         uint32_t b0, uint32_t b1) {
    asm("mma.sync.aligned.m16n8k8.row.col.f32.tf32.tf32.f32 "
        "{%0,%1,%2,%3}, {%4,%5,%6,%7}, {%8,%9}, {%0,%1,%2,%3};"
        : "+f"(d0), "+f"(d1), "+f"(d2), "+f"(d3)
        : "r"(a0), "r"(a1), "r"(a2), "r"(a3), "r"(b0), "r"(b1));
}

// ---------------------------------------------------------------------------
// tf32 tensor-core GEMM (unchanged from R7): C = A @ B + bias
// ---------------------------------------------------------------------------
constexpr int GBK = 16;
constexpr int GPAD = 136;

__global__ __launch_bounds__(256, 2)
void gemm_tf32(const float* __restrict__ A, const float* __restrict__ Bm,
               const float* __restrict__ bias, float* __restrict__ C,
               int M, int N, int K)
{
    __shared__ uint32_t As[GBK][GPAD];   // [k][m]
    __shared__ uint32_t Bs[GBK][GPAD];   // [k][n]

    const int tid  = threadIdx.x;
    const int lane = tid & 31;
    const int wid  = tid >> 5;
    const int wm   = (wid >> 2) * 64;
    const int wn   = (wid & 3) * 32;
    const int m0 = blockIdx.y * 128;
    const int n0 = blockIdx.x * 128;

    const int am  = tid & 127;
    const int akc = (tid >> 7) * 4;
    const int bk = tid >> 5;
    const int bc = (tid & 31) * 4;

    const float* Aptr = A + (size_t)(m0 + am) * K + akc;
    const float* Bptr = Bm + (size_t)bk * N + n0 + bc;

    float4 ra0 = *(const float4*)(Aptr);
    float4 ra1 = *(const float4*)(Aptr + 8);
    float4 rb0 = *(const float4*)(Bptr);
    float4 rb1 = *(const float4*)(Bptr + (size_t)8 * N);

    float acc[4][4][4];
    #pragma unroll
    for (int i = 0; i < 4; i++)
        #pragma unroll
        for (int j = 0; j < 4; j++)
            #pragma unroll
            for (int t = 0; t < 4; t++) acc[i][j][t] = 0.f;

    const int kq = lane & 3;
    const int gq = lane >> 2;

    for (int k0 = 0; k0 < K; k0 += GBK) {
        As[akc + 0][am] = f2tf32(ra0.x);  As[akc + 1][am] = f2tf32(ra0.y);
        As[akc + 2][am] = f2tf32(ra0.z);  As[akc + 3][am] = f2tf32(ra0.w);
        As[akc + 8][am] = f2tf32(ra1.x);  As[akc + 9][am] = f2tf32(ra1.y);
        As[akc + 10][am] = f2tf32(ra1.z); As[akc + 11][am] = f2tf32(ra1.w);
        {
            uint4 q0 = make_uint4(f2tf32(rb0.x), f2tf32(rb0.y), f2tf32(rb0.z), f2tf32(rb0.w));
            uint4 q1 = make_uint4(f2tf32(rb1.x), f2tf32(rb1.y), f2tf32(rb1.z), f2tf32(rb1.w));
            *(uint4*)&Bs[bk][bc]     = q0;
            *(uint4*)&Bs[bk + 8][bc] = q1;
        }
        __syncthreads();

        if (k0 + GBK < K) {
            ra0 = *(const float4*)(Aptr + k0 + GBK);
            ra1 = *(const float4*)(Aptr + k0 + GBK + 8);
            rb0 = *(const float4*)(Bptr + (size_t)(k0 + GBK) * N);
            rb1 = *(const float4*)(Bptr + (size_t)(k0 + GBK + 8) * N);
        }

        #pragma unroll
        for (int ks = 0; ks < GBK; ks += 8) {
            const int kk = ks + kq;
            uint32_t af[4][4], bf[4][2];
            #pragma unroll
            for (int i = 0; i < 4; i++) {
                const int mi = wm + i * 16 + gq;
                af[i][0] = As[kk][mi];
                af[i][1] = As[kk][mi + 8];
                af[i][2] = As[kk + 4][mi];
                af[i][3] = As[kk + 4][mi + 8];
            }
            #pragma unroll
            for (int j = 0; j < 4; j++) {
                const int nj = wn + j * 8 + gq;
                bf[j][0] = Bs[kk][nj];
                bf[j][1] = Bs[kk + 4][nj];
            }
            #pragma unroll
            for (int i = 0; i < 4; i++)
                #pragma unroll
                for (int j = 0; j < 4; j++)
                    mma_tf32(acc[i][j][0], acc[i][j][1], acc[i][j][2], acc[i][j][3],
                             af[i][0], af[i][1], af[i][2], af[i][3],
                             bf[j][0], bf[j][1]);
        }
        __syncthreads();
    }

    #pragma unroll
    for (int j = 0; j < 4; j++) {
        const int col = n0 + wn + j * 8 + 2 * kq;
        const float bi0 = bias[col];
        const float bi1 = bias[col + 1];
        #pragma unroll
        for (int i = 0; i < 4; i++) {
            const int row = m0 + wm + i * 16 + gq;
            float2 v0 = make_float2(acc[i][j][0] + bi0, acc[i][j][1] + bi1);
            float2 v1 = make_float2(acc[i][j][2] + bi0, acc[i][j][3] + bi1);
            *(float2*)&C[(size_t)row * N + col]       = v0;
            *(float2*)&C[(size_t)(row + 8) * N + col] = v1;
        }
    }
}

// ---------------------------------------------------------------------------
// Tensor-core flash attention (tf32 mma), causal. BQ=128, BKV=64, HD=64.
// 8 warps; warp w owns q-rows [16w,16w+16) x all 64 kv cols -> warp-local
// softmax. Q frags live in registers (32/thread) for the whole kernel.
// smem: Kt[d][kv] tf32, Vs[kv][d] tf32, Ps[q][kv] tf32 (aliases Q staging).
// ---------------------------------------------------------------------------
constexpr int F_BQ  = 128;
constexpr int F_KST = 72;    // Kt/Vs stride: frag LDS -> 8*kq+gq, conflict-free
constexpr int F_PST = 68;    // Ps stride:    frag LDS -> 4*gq+kq, conflict-free
constexpr int F_QST = 136;   // Q staging stride
constexpr int F_SM_VS = 64 * F_KST;          // 4608
constexpr int F_SM_PS = 2 * 64 * F_KST;      // 9216
constexpr int FLASH_SMEM = (F_SM_PS + F_BQ * F_PST) * 4;  // (9216+8704)*4 = 71680 B

__global__ __launch_bounds__(256, 2) void flash_attn_tc()
{
    extern __shared__ float sm[];
    uint32_t* Kt = (uint32_t*)sm;               // [64][72]  (Kt[d][kv], tf32 bits)
    uint32_t* Vs = (uint32_t*)(sm + F_SM_VS);   // [64][72]  (Vs[kv][d], tf32 bits)
    uint32_t* Ps = (uint32_t*)(sm + F_SM_PS);   // [128][68] (P tf32 bits)
    float*    Qt = sm + F_SM_PS;                // staging alias [64][136] (fp32)

    const int tid  = threadIdx.x;
    const int lane = tid & 31;
    const int w    = tid >> 5;
    const int kq   = lane & 3;
    const int gq   = lane >> 2;
    const int qb   = gridDim.x - 1 - blockIdx.x;   // heavy blocks first
    const int q0   = qb * F_BQ;
    const int h    = blockIdx.y;
    const int b    = blockIdx.z;
    const int m0w  = w * 16;

    const float* qkv_b = g_qkv + (size_t)b * TT * D3;

    // ---- Q staging (scaled by 1/sqrt(64)=0.125), transposed [d][q]
    {
        const int qr = tid & 127;
        const int dc = (tid >> 7) * 32;
        const float* qp = qkv_b + (size_t)(q0 + qr) * D3 + h * HDD + dc;
        #pragma unroll
        for (int c = 0; c < 8; c++) {
            float4 q4 = *(const float4*)(qp + 4 * c);
            Qt[(dc + 4 * c + 0) * F_QST + qr] = q4.x * 0.125f;
            Qt[(dc + 4 * c + 1) * F_QST + qr] = q4.y * 0.125f;
            Qt[(dc + 4 * c + 2) * F_QST + qr] = q4.z * 0.125f;
            Qt[(dc + 4 * c + 3) * F_QST + qr] = q4.w * 0.125f;
        }
    }
    __syncthreads();

    // ---- Q fragments -> registers (persist across kv tiles)
    uint32_t qf[8][4];
    #pragma unroll
    for (int ks = 0; ks < 8; ks++) {
        const int d0 = ks * 8 + kq;
        qf[ks][0] = f2tf32(Qt[d0 * F_QST + m0w + gq]);
        qf[ks][1] = f2tf32(Qt[d0 * F_QST + m0w + gq + 8]);
        qf[ks][2] = f2tf32(Qt[(d0 + 4) * F_QST + m0w + gq]);
        qf[ks][3] = f2tf32(Qt[(d0 + 4) * F_QST + m0w + gq + 8]);
    }
    __syncthreads();   // Qt now reusable as Ps

    float oacc[8][4];
    #pragma unroll
    for (int j = 0; j < 8; j++)
        #pragma unroll
        for (int t = 0; t < 4; t++) oacc[j][t] = 0.f;
    float m_r[2] = { -1e30f, -1e30f };
    float l_r[2] = { 0.f, 0.f };

    const int nt = 2 * qb + 2;
    for (int it = 0; it < nt; it++) {
        __syncthreads();   // prior tile's Kt/Vs/Ps reads complete
        // ---- K (transposed) / V (natural) load, tf32 conversion at STS
        {
            const int krow = tid & 63;
            const int kdc  = (tid >> 6) * 16;
            const float* kp = qkv_b + (size_t)(it * 64 + krow) * D3 + DD + h * HDD + kdc;
            #pragma unroll
            for (int c = 0; c < 4; c++) {
                float4 k4 = *(const float4*)(kp + 4 * c);
                Kt[(kdc + 4 * c + 0) * F_KST + krow] = f2tf32(k4.x);
                Kt[(kdc + 4 * c + 1) * F_KST + krow] = f2tf32(k4.y);
                Kt[(kdc + 4 * c + 2) * F_KST + krow] = f2tf32(k4.z);
                Kt[(kdc + 4 * c + 3) * F_KST + krow] = f2tf32(k4.w);
            }
            const int vrow = tid >> 2;
            const int vdc  = (tid & 3) * 16;
            const float* vp = qkv_b + (size_t)(it * 64 + vrow) * D3 + 2 * DD + h * HDD + vdc;
            #pragma unroll
            for (int c = 0; c < 4; c++) {
                float4 v4 = *(const float4*)(vp + 4 * c);
                uint4 u = make_uint4(f2tf32(v4.x), f2tf32(v4.y), f2tf32(v4.z), f2tf32(v4.w));
                *(uint4*)&Vs[vrow * F_KST + vdc + 4 * c] = u;
            }
        }
        __syncthreads();

        // ---- S = Q @ K^T  (warp tile 16x64; 4 interleaved acc chains)
        float sacc[8][4];
        #pragma unroll
        for (int j = 0; j < 8; j++)
            #pragma unroll
            for (int t = 0; t < 4; t++) sacc[j][t] = 0.f;

        #pragma unroll
        for (int jb = 0; jb < 8; jb += 4) {
            #pragma unroll
            for (int ks = 0; ks < 8; ks++) {
                const int d0 = ks * 8 + kq;
                #pragma unroll
                for (int jj = 0; jj < 4; jj++) {
                    const int nj = (jb + jj) * 8 + gq;
                    uint32_t b0 = Kt[d0 * F_KST + nj];
                    uint32_t b1 = Kt[(d0 + 4) * F_KST + nj];
                    mma_tf32(sacc[jb + jj][0], sacc[jb + jj][1],
                             sacc[jb + jj][2], sacc[jb + jj][3],
                             qf[ks][0], qf[ks][1], qf[ks][2], qf[ks][3], b0, b1);
                }
            }
        }

        // ---- causal mask (only the two diagonal-region tiles)
        const int r0g = q0 + m0w + gq;
        const int r1g = r0g + 8;
        if (it >= nt - 2) {
            const int cb = it * 64 + 2 * kq;
            #pragma unroll
            for (int j = 0; j < 8; j++) {
                const int c = cb + j * 8;
                if (c     > r0g) sacc[j][0] = -1e30f;
                if (c + 1 > r0g) sacc[j][1] = -1e30f;
                if (c     > r1g) sacc[j][2] = -1e30f;
                if (c + 1 > r1g) sacc[j][3] = -1e30f;
            }
        }

        // ---- online softmax (rows gq and gq+8; quad-lane reductions)
        float mx0 = -1e30f, mx1 = -1e30f;
        #pragma unroll
        for (int j = 0; j < 8; j++) {
            mx0 = fmaxf(mx0, fmaxf(sacc[j][0], sacc[j][1]));
            mx1 = fmaxf(mx1, fmaxf(sacc[j][2], sacc[j][3]));
        }
        mx0 = fmaxf(mx0, __shfl_xor_sync(0xffffffffu, mx0, 1));
        mx0 = fmaxf(mx0, __shfl_xor_sync(0xffffffffu, mx0, 2));
        mx1 = fmaxf(mx1, __shfl_xor_sync(0xffffffffu, mx1, 1));
        mx1 = fmaxf(mx1, __shfl_xor_sync(0xffffffffu, mx1, 2));

        const float mn0 = fmaxf(m_r[0], mx0);
        const float mn1 = fmaxf(m_r[1], mx1);
        const float al0 = __expf(m_r[0] - mn0);
        const float al1 = __expf(m_r[1] - mn1);

        float ps0 = 0.f, ps1 = 0.f;
        #pragma unroll
        for (int j = 0; j < 8; j++) {
            sacc[j][0] = __expf(sacc[j][0] - mn0);
            sacc[j][1] = __expf(sacc[j][1] - mn0);
            sacc[j][2] = __expf(sacc[j][2] - mn1);
            sacc[j][3] = __expf(sacc[j][3] - mn1);
            ps0 += sacc[j][0] + sacc[j][1];
            ps1 += sacc[j][2] + sacc[j][3];
        }
        ps0 += __shfl_xor_sync(0xffffffffu, ps0, 1);
        ps0 += __shfl_xor_sync(0xffffffffu, ps0, 2);
        ps1 += __shfl_xor_sync(0xffffffffu, ps1, 1);
        ps1 += __shfl_xor_sync(0xffffffffu, ps1, 2);

        l_r[0] = l_r[0] * al0 + ps0;  m_r[0] = mn0;
        l_r[1] = l_r[1] * al1 + ps1;  m_r[1] = mn1;
        #pragma unroll
        for (int j = 0; j < 8; j++) {
            oacc[j][0] *= al0;  oacc[j][1] *= al0;
            oacc[j][2] *= al1;  oacc[j][3] *= al1;
        }

        // ---- P -> smem (tf32 bits); warp-local consumption only
        #pragma unroll
        for (int j = 0; j < 8; j++) {
            uint2 p0 = make_uint2(f2tf32(sacc[j][0]), f2tf32(sacc[j][1]));
            uint2 p1 = make_uint2(f2tf32(sacc[j][2]), f2tf32(sacc[j][3]));
            *(uint2*)&Ps[(m0w + gq) * F_PST + j * 8 + 2 * kq]     = p0;
            *(uint2*)&Ps[(m0w + 8 + gq) * F_PST + j * 8 + 2 * kq] = p1;
        }
        __syncwarp();

        // ---- O += P @ V  (8 independent acc chains)
        #pragma unroll
        for (int ks = 0; ks < 8; ks++) {
            const int kv0 = ks * 8 + kq;
            uint32_t pa0 = Ps[(m0w + gq) * F_PST + kv0];
            uint32_t pa1 = Ps[(m0w + 8 + gq) * F_PST + kv0];
            uint32_t pa2 = Ps[(m0w + gq) * F_PST + kv0 + 4];
            uint32_t pa3 = Ps[(m0w + 8 + gq) * F_PST + kv0 + 4];
            #pragma unroll
            for (int j = 0; j < 8; j++) {
                uint32_t b0 = Vs[kv0 * F_KST + j * 8 + gq];
                uint32_t b1 = Vs[(kv0 + 4) * F_KST + j * 8 + gq];
                mma_tf32(oacc[j][0], oacc[j][1], oacc[j][2], oacc[j][3],
                         pa0, pa1, pa2, pa3, b0, b1);
            }
        }
    }

    // ---- epilogue
    const float inv0 = 1.f / l_r[0];
    const float inv1 = 1.f / l_r[1];
    const int r0g = q0 + m0w + gq;
    #pragma unroll
    for (int j = 0; j < 8; j++) {
        const int col = h * HDD + j * 8 + 2 * kq;
        float2 v0 = make_float2(oacc[j][0] * inv0, oacc[j][1] * inv0);
        float2 v1 = make_float2(oacc[j][2] * inv1, oacc[j][3] * inv1);
        *(float2*)&g_y[(size_t)(b * TT + r0g) * DD + col]     = v0;
        *(float2*)&g_y[(size_t)(b * TT + r0g + 8) * DD + col] = v1;
    }
}

// ---------------------------------------------------------------------------
extern "C" void kernel_launch(void* const* d_in, const int* in_sizes, int n_in,
                              void* d_out, int out_size)
{
    const float* x     = (const float*)d_in[0];
    const float* Wqkv  = (const float*)d_in[1];
    const float* bqkv  = (const float*)d_in[2];
    const float* Wproj = (const float*)d_in[3];
    const float* bproj = (const float*)d_in[4];
    float* out = (float*)d_out;

    float *qkv_ptr, *y_ptr;
    cudaGetSymbolAddress((void**)&qkv_ptr, g_qkv);
    cudaGetSymbolAddress((void**)&y_ptr, g_y);

    cudaFuncSetAttribute(flash_attn_tc, cudaFuncAttributeMaxDynamicSharedMemorySize, FLASH_SMEM);

    // 1) QKV = x @ Wqkv + bqkv       [4096,1024] @ [1024,3072]
    gemm_tf32<<<dim3(D3 / 128, BT / 128), 256>>>(x, Wqkv, bqkv, qkv_ptr, BT, D3, DD);

    // 2) causal flash attention (tensor cores) -> g_y [B,T,D]
    flash_attn_tc<<<dim3(TT / F_BQ, NHH, BB), 256, FLASH_SMEM>>>();

    // 3) out = y @ Wproj + bproj     [4096,1024] @ [1024,1024]
    gemm_tf32<<<dim3(DD / 128, BT / 128), 256>>>(y_ptr, Wproj, bproj, out, BT, DD, DD);
}

// round 10
// speedup vs baseline: 8.0346x; 1.6782x over previous
#include <cuda_runtime.h>
#include <math.h>
#include <stdint.h>

#define BB 2
#define TT 2048
#define DD 1024
#define NHH 16
#define HDD 64
constexpr int BT = BB * TT;          // 4096 rows
constexpr int D3 = 3 * DD;           // 3072

// Scratch (no allocations allowed)
__device__ float g_qkv[BB * TT * D3];   // [B,T,3D]
__device__ float g_y[BB * TT * DD];     // [B,T,D]

// ---- helpers ----
__device__ __forceinline__ uint32_t f2tf32(float f) {
    uint32_t r; asm("cvt.rna.tf32.f32 %0, %1;" : "=r"(r) : "f"(f)); return r;
}
__device__ __forceinline__ void mma_tf32(float& d0, float& d1, float& d2, float& d3,
                                         uint32_t a0, uint32_t a1, uint32_t a2, uint32_t a3,
                                         uint32_t b0, uint32_t b1) {
    asm("mma.sync.aligned.m16n8k8.row.col.f32.tf32.tf32.f32 "
        "{%0,%1,%2,%3}, {%4,%5,%6,%7}, {%8,%9}, {%0,%1,%2,%3};"
        : "+f"(d0), "+f"(d1), "+f"(d2), "+f"(d3)
        : "r"(a0), "r"(a1), "r"(a2), "r"(a3), "r"(b0), "r"(b1));
}
__device__ __forceinline__ float ex2(float x) {
    float y; asm("ex2.approx.ftz.f32 %0, %1;" : "=f"(y) : "f"(x)); return y;
}

// ---------------------------------------------------------------------------
// tf32 tensor-core GEMM: C = A @ B + bias
// BM=BN=128, BK=16, 256 threads, 8 warps (2x4, 64x32 warp tile).
// Paired smem layout [ks*4+kq][m|n][kr] -> every frag fetch is one LDS.64.
// Double-buffered smem, one barrier per K-slice.
// ---------------------------------------------------------------------------
constexpr int GP = 132;

__global__ __launch_bounds__(256, 2)
void gemm_tf32(const float* __restrict__ A, const float* __restrict__ Bm,
               const float* __restrict__ bias, float* __restrict__ C,
               int M, int N, int K)
{
    __shared__ uint32_t As2[2][8][GP][2];   // [stage][ksq][m][kr]
    __shared__ uint32_t Bs2[2][8][GP][2];   // [stage][ksq][n][kr]

    const int tid  = threadIdx.x;
    const int lane = tid & 31;
    const int wid  = tid >> 5;
    const int wm   = (wid >> 2) * 64;
    const int wn   = (wid & 3) * 32;
    const int m0 = blockIdx.y * 128;
    const int n0 = blockIdx.x * 128;
    const int kq = lane & 3;
    const int gq = lane >> 2;

    // A loader: thread covers (m0+am, k in {4ah..4ah+3, 8+4ah..8+4ah+3})
    const int am = tid & 127;
    const int ah = tid >> 7;                  // 0/1 -> kr
    const float* Aptr = A + (size_t)(m0 + am) * K + ah * 4;

    // B loader: k_lo = kh*8+kqb (kr=0), k_hi = k_lo+4 (kr=1), 4 cols
    const int kqb = (tid >> 5) & 3;
    const int kh  = tid >> 7;
    const int bc  = (tid & 31) * 4;
    const float* BptrL = Bm + (size_t)(kh * 8 + kqb) * N + n0 + bc;
    const float* BptrH = BptrL + (size_t)4 * N;

    float4 ra0 = *(const float4*)(Aptr);
    float4 ra1 = *(const float4*)(Aptr + 8);
    float4 rb0 = *(const float4*)(BptrL);
    float4 rb1 = *(const float4*)(BptrH);

    float acc[4][4][4];
    #pragma unroll
    for (int i = 0; i < 4; i++)
        #pragma unroll
        for (int j = 0; j < 4; j++)
            #pragma unroll
            for (int t = 0; t < 4; t++) acc[i][j][t] = 0.f;

    // store tile 0 into stage 0
    {
        float a0v[4] = { ra0.x, ra0.y, ra0.z, ra0.w };
        float a1v[4] = { ra1.x, ra1.y, ra1.z, ra1.w };
        #pragma unroll
        for (int j = 0; j < 4; j++) {
            As2[0][j][am][ah]     = f2tf32(a0v[j]);
            As2[0][4 + j][am][ah] = f2tf32(a1v[j]);
        }
        uint4 u0 = make_uint4(f2tf32(rb0.x), f2tf32(rb1.x), f2tf32(rb0.y), f2tf32(rb1.y));
        uint4 u1 = make_uint4(f2tf32(rb0.z), f2tf32(rb1.z), f2tf32(rb0.w), f2tf32(rb1.w));
        *(uint4*)&Bs2[0][kh * 4 + kqb][bc][0]     = u0;
        *(uint4*)&Bs2[0][kh * 4 + kqb][bc + 2][0] = u1;
    }
    __syncthreads();

    for (int k0 = 0; k0 < K; k0 += 16) {
        const int st = (k0 >> 4) & 1;
        const bool more = (k0 + 16) < K;
        if (more) {   // prefetch next tile into regs
            ra0 = *(const float4*)(Aptr + k0 + 16);
            ra1 = *(const float4*)(Aptr + k0 + 24);
            rb0 = *(const float4*)(BptrL + (size_t)(k0 + 16) * N);
            rb1 = *(const float4*)(BptrH + (size_t)(k0 + 16) * N);
        }

        #pragma unroll
        for (int s = 0; s < 2; s++) {
            const int ksq = s * 4 + kq;
            uint32_t af[4][4], bf[4][2];
            #pragma unroll
            for (int i = 0; i < 4; i++) {
                uint2 alo = *(const uint2*)&As2[st][ksq][wm + 16 * i + gq][0];
                uint2 ahi = *(const uint2*)&As2[st][ksq][wm + 16 * i + gq + 8][0];
                af[i][0] = alo.x; af[i][1] = ahi.x; af[i][2] = alo.y; af[i][3] = ahi.y;
            }
            #pragma unroll
            for (int j = 0; j < 4; j++) {
                uint2 bp = *(const uint2*)&Bs2[st][ksq][wn + 8 * j + gq][0];
                bf[j][0] = bp.x; bf[j][1] = bp.y;
            }
            #pragma unroll
            for (int i = 0; i < 4; i++)
                #pragma unroll
                for (int j = 0; j < 4; j++)
                    mma_tf32(acc[i][j][0], acc[i][j][1], acc[i][j][2], acc[i][j][3],
                             af[i][0], af[i][1], af[i][2], af[i][3],
                             bf[j][0], bf[j][1]);
        }

        if (more) {   // store prefetched tile into the other stage
            const int st2 = st ^ 1;
            float a0v[4] = { ra0.x, ra0.y, ra0.z, ra0.w };
            float a1v[4] = { ra1.x, ra1.y, ra1.z, ra1.w };
            #pragma unroll
            for (int j = 0; j < 4; j++) {
                As2[st2][j][am][ah]     = f2tf32(a0v[j]);
                As2[st2][4 + j][am][ah] = f2tf32(a1v[j]);
            }
            uint4 u0 = make_uint4(f2tf32(rb0.x), f2tf32(rb1.x), f2tf32(rb0.y), f2tf32(rb1.y));
            uint4 u1 = make_uint4(f2tf32(rb0.z), f2tf32(rb1.z), f2tf32(rb0.w), f2tf32(rb1.w));
            *(uint4*)&Bs2[st2][kh * 4 + kqb][bc][0]     = u0;
            *(uint4*)&Bs2[st2][kh * 4 + kqb][bc + 2][0] = u1;
            __syncthreads();
        }
    }

    #pragma unroll
    for (int j = 0; j < 4; j++) {
        const int col = n0 + wn + j * 8 + 2 * kq;
        const float bi0 = bias[col];
        const float bi1 = bias[col + 1];
        #pragma unroll
        for (int i = 0; i < 4; i++) {
            const int row = m0 + wm + i * 16 + gq;
            float2 v0 = make_float2(acc[i][j][0] + bi0, acc[i][j][1] + bi1);
            float2 v1 = make_float2(acc[i][j][2] + bi0, acc[i][j][3] + bi1);
            *(float2*)&C[(size_t)row * N + col]       = v0;
            *(float2*)&C[(size_t)(row + 8) * N + col] = v1;
        }
    }
}

// ---------------------------------------------------------------------------
// Tensor-core flash attention (tf32 mma), causal. BQ=128, BKV=64, HD=64.
// Paired K/V smem layouts -> LDS.64 frag fetches. ex2-domain softmax.
// ---------------------------------------------------------------------------
constexpr int F_BQ  = 128;
constexpr int F_PST = 68;
constexpr int F_QST = 136;
constexpr int F_KP_W = 32 * 68 * 2;                        // 4352 words each
constexpr int FLASH_SMEM = (2 * F_KP_W + F_BQ * F_PST) * 4;  // 69632 B
constexpr float QSCALE = 0.125f * 1.44269504088896f;        // 1/sqrt(64) * log2(e)

__global__ __launch_bounds__(256, 2) void flash_attn_tc()
{
    extern __shared__ float sm[];
    uint32_t* Kp = (uint32_t*)sm;          // [ksq=(d>>3)*4+(d&3)][kv][kr=(d>>2)&1]
    uint32_t* Vp = Kp + F_KP_W;            // [ksq=(kv>>3)*4+(kv&3)][d][kr=(kv>>2)&1]
    uint32_t* Ps = Vp + F_KP_W;            // [128][68] tf32 bits
    float*    Qt = (float*)Ps;             // staging alias [64][136] fp32

    const int tid  = threadIdx.x;
    const int lane = tid & 31;
    const int w    = tid >> 5;
    const int kq   = lane & 3;
    const int gq   = lane >> 2;
    const int qb   = gridDim.x - 1 - blockIdx.x;   // heavy blocks first
    const int q0   = qb * F_BQ;
    const int h    = blockIdx.y;
    const int b    = blockIdx.z;
    const int m0w  = w * 16;

    const float* qkv_b = g_qkv + (size_t)b * TT * D3;

    // ---- Q staging (scaled into log2 domain), transposed [d][q]
    {
        const int qr = tid & 127;
        const int dc = (tid >> 7) * 32;
        const float* qp = qkv_b + (size_t)(q0 + qr) * D3 + h * HDD + dc;
        #pragma unroll
        for (int c = 0; c < 8; c++) {
            float4 q4 = *(const float4*)(qp + 4 * c);
            Qt[(dc + 4 * c + 0) * F_QST + qr] = q4.x * QSCALE;
            Qt[(dc + 4 * c + 1) * F_QST + qr] = q4.y * QSCALE;
            Qt[(dc + 4 * c + 2) * F_QST + qr] = q4.z * QSCALE;
            Qt[(dc + 4 * c + 3) * F_QST + qr] = q4.w * QSCALE;
        }
    }
    __syncthreads();

    // ---- Q fragments -> registers (persist)
    uint32_t qf[8][4];
    #pragma unroll
    for (int ks = 0; ks < 8; ks++) {
        const int d0 = ks * 8 + kq;
        qf[ks][0] = f2tf32(Qt[d0 * F_QST + m0w + gq]);
        qf[ks][1] = f2tf32(Qt[d0 * F_QST + m0w + gq + 8]);
        qf[ks][2] = f2tf32(Qt[(d0 + 4) * F_QST + m0w + gq]);
        qf[ks][3] = f2tf32(Qt[(d0 + 4) * F_QST + m0w + gq + 8]);
    }
    __syncthreads();   // Qt now reusable as Ps

    float oacc[8][4];
    #pragma unroll
    for (int j = 0; j < 8; j++)
        #pragma unroll
        for (int t = 0; t < 4; t++) oacc[j][t] = 0.f;
    float m_r[2] = { -1e30f, -1e30f };
    float l_r[2] = { 0.f, 0.f };

    // V-store constants (per-thread fixed kv row)
    const int vrow = tid >> 2;
    const int vdc  = (tid & 3) * 16;
    const int vksq = (vrow >> 3) * 4 + (vrow & 3);
    const int vkr  = (vrow >> 2) & 1;
    const int krow = tid & 63;
    const int kdc  = (tid >> 6) * 16;

    const int nt = 2 * qb + 2;
    for (int it = 0; it < nt; it++) {
        __syncthreads();
        // ---- K (d-pairs) / V (kv-pairs), tf32 at STS
        {
            const float* kpg = qkv_b + (size_t)(it * 64 + krow) * D3 + DD + h * HDD + kdc;
            #pragma unroll
            for (int c = 0; c < 4; c++) {
                float4 k4 = *(const float4*)(kpg + 4 * c);
                const int db  = kdc + 4 * c;
                const int ksq = (db >> 3) * 4;
                const int kr  = (db >> 2) & 1;
                Kp[((ksq + 0) * 68 + krow) * 2 + kr] = f2tf32(k4.x);
                Kp[((ksq + 1) * 68 + krow) * 2 + kr] = f2tf32(k4.y);
                Kp[((ksq + 2) * 68 + krow) * 2 + kr] = f2tf32(k4.z);
                Kp[((ksq + 3) * 68 + krow) * 2 + kr] = f2tf32(k4.w);
            }
            const float* vpg = qkv_b + (size_t)(it * 64 + vrow) * D3 + 2 * DD + h * HDD + vdc;
            #pragma unroll
            for (int c = 0; c < 4; c++) {
                float4 v4 = *(const float4*)(vpg + 4 * c);
                const int d = vdc + 4 * c;
                Vp[(vksq * 68 + d + 0) * 2 + vkr] = f2tf32(v4.x);
                Vp[(vksq * 68 + d + 1) * 2 + vkr] = f2tf32(v4.y);
                Vp[(vksq * 68 + d + 2) * 2 + vkr] = f2tf32(v4.z);
                Vp[(vksq * 68 + d + 3) * 2 + vkr] = f2tf32(v4.w);
            }
        }
        __syncthreads();

        // ---- S = Q @ K^T (LDS.64 per frag pair)
        float sacc[8][4];
        #pragma unroll
        for (int j = 0; j < 8; j++)
            #pragma unroll
            for (int t = 0; t < 4; t++) sacc[j][t] = 0.f;

        #pragma unroll
        for (int ks = 0; ks < 8; ks++) {
            const int row = ks * 4 + kq;
            #pragma unroll
            for (int j = 0; j < 8; j++) {
                uint2 kp2 = *(const uint2*)&Kp[(row * 68 + 8 * j + gq) * 2];
                mma_tf32(sacc[j][0], sacc[j][1], sacc[j][2], sacc[j][3],
                         qf[ks][0], qf[ks][1], qf[ks][2], qf[ks][3],
                         kp2.x, kp2.y);
            }
        }

        // ---- causal mask (diagonal-region tiles only)
        const int r0g = q0 + m0w + gq;
        const int r1g = r0g + 8;
        if (it >= nt - 2) {
            const int cb = it * 64 + 2 * kq;
            #pragma unroll
            for (int j = 0; j < 8; j++) {
                const int c = cb + j * 8;
                if (c     > r0g) sacc[j][0] = -1e30f;
                if (c + 1 > r0g) sacc[j][1] = -1e30f;
                if (c     > r1g) sacc[j][2] = -1e30f;
                if (c + 1 > r1g) sacc[j][3] = -1e30f;
            }
        }

        // ---- online softmax in log2 domain (quad reductions)
        float mx0 = -1e30f, mx1 = -1e30f;
        #pragma unroll
        for (int j = 0; j < 8; j++) {
            mx0 = fmaxf(mx0, fmaxf(sacc[j][0], sacc[j][1]));
            mx1 = fmaxf(mx1, fmaxf(sacc[j][2], sacc[j][3]));
        }
        mx0 = fmaxf(mx0, __shfl_xor_sync(0xffffffffu, mx0, 1));
        mx0 = fmaxf(mx0, __shfl_xor_sync(0xffffffffu, mx0, 2));
        mx1 = fmaxf(mx1, __shfl_xor_sync(0xffffffffu, mx1, 1));
        mx1 = fmaxf(mx1, __shfl_xor_sync(0xffffffffu, mx1, 2));

        const float mn0 = fmaxf(m_r[0], mx0);
        const float mn1 = fmaxf(m_r[1], mx1);
        const float al0 = ex2(m_r[0] - mn0);
        const float al1 = ex2(m_r[1] - mn1);

        float ps0 = 0.f, ps1 = 0.f;
        #pragma unroll
        for (int j = 0; j < 8; j++) {
            sacc[j][0] = ex2(sacc[j][0] - mn0);
            sacc[j][1] = ex2(sacc[j][1] - mn0);
            sacc[j][2] = ex2(sacc[j][2] - mn1);
            sacc[j][3] = ex2(sacc[j][3] - mn1);
            ps0 += sacc[j][0] + sacc[j][1];
            ps1 += sacc[j][2] + sacc[j][3];
        }
        ps0 += __shfl_xor_sync(0xffffffffu, ps0, 1);
        ps0 += __shfl_xor_sync(0xffffffffu, ps0, 2);
        ps1 += __shfl_xor_sync(0xffffffffu, ps1, 1);
        ps1 += __shfl_xor_sync(0xffffffffu, ps1, 2);

        l_r[0] = l_r[0] * al0 + ps0;  m_r[0] = mn0;
        l_r[1] = l_r[1] * al1 + ps1;  m_r[1] = mn1;
        #pragma unroll
        for (int j = 0; j < 8; j++) {
            oacc[j][0] *= al0;  oacc[j][1] *= al0;
            oacc[j][2] *= al1;  oacc[j][3] *= al1;
        }

        // ---- P -> smem (warp-local)
        #pragma unroll
        for (int j = 0; j < 8; j++) {
            uint2 p0 = make_uint2(f2tf32(sacc[j][0]), f2tf32(sacc[j][1]));
            uint2 p1 = make_uint2(f2tf32(sacc[j][2]), f2tf32(sacc[j][3]));
            *(uint2*)&Ps[(m0w + gq) * F_PST + j * 8 + 2 * kq]     = p0;
            *(uint2*)&Ps[(m0w + 8 + gq) * F_PST + j * 8 + 2 * kq] = p1;
        }
        __syncwarp();

        // ---- O += P @ V (LDS.64 V pairs)
        #pragma unroll
        for (int ks = 0; ks < 8; ks++) {
            const int kv0 = ks * 8 + kq;
            const int row = ks * 4 + kq;
            uint32_t pa0 = Ps[(m0w + gq) * F_PST + kv0];
            uint32_t pa1 = Ps[(m0w + 8 + gq) * F_PST + kv0];
            uint32_t pa2 = Ps[(m0w + gq) * F_PST + kv0 + 4];
            uint32_t pa3 = Ps[(m0w + 8 + gq) * F_PST + kv0 + 4];
            #pragma unroll
            for (int j = 0; j < 8; j++) {
                uint2 vp2 = *(const uint2*)&Vp[(row * 68 + 8 * j + gq) * 2];
                mma_tf32(oacc[j][0], oacc[j][1], oacc[j][2], oacc[j][3],
                         pa0, pa1, pa2, pa3, vp2.x, vp2.y);
            }
        }
    }

    // ---- epilogue
    const float inv0 = 1.f / l_r[0];
    const float inv1 = 1.f / l_r[1];
    const int r0g = q0 + m0w + gq;
    #pragma unroll
    for (int j = 0; j < 8; j++) {
        const int col = h * HDD + j * 8 + 2 * kq;
        float2 v0 = make_float2(oacc[j][0] * inv0, oacc[j][1] * inv0);
        float2 v1 = make_float2(oacc[j][2] * inv1, oacc[j][3] * inv1);
        *(float2*)&g_y[(size_t)(b * TT + r0g) * DD + col]     = v0;
        *(float2*)&g_y[(size_t)(b * TT + r0g + 8) * DD + col] = v1;
    }
}

// ---------------------------------------------------------------------------
extern "C" void kernel_launch(void* const* d_in, const int* in_sizes, int n_in,
                              void* d_out, int out_size)
{
    const float* x     = (const float*)d_in[0];
    const float* Wqkv  = (const float*)d_in[1];
    const float* bqkv  = (const float*)d_in[2];
    const float* Wproj = (const float*)d_in[3];
    const float* bproj = (const float*)d_in[4];
    float* out = (float*)d_out;

    float *qkv_ptr, *y_ptr;
    cudaGetSymbolAddress((void**)&qkv_ptr, g_qkv);
    cudaGetSymbolAddress((void**)&y_ptr, g_y);

    cudaFuncSetAttribute(flash_attn_tc, cudaFuncAttributeMaxDynamicSharedMemorySize, FLASH_SMEM);

    // 1) QKV = x @ Wqkv + bqkv       [4096,1024] @ [1024,3072]
    gemm_tf32<<<dim3(D3 / 128, BT / 128), 256>>>(x, Wqkv, bqkv, qkv_ptr, BT, D3, DD);

    // 2) causal flash attention (tensor cores) -> g_y [B,T,D]
    flash_attn_tc<<<dim3(TT / F_BQ, NHH, BB), 256, FLASH_SMEM>>>();

    // 3) out = y @ Wproj + bproj     [4096,1024] @ [1024,1024]
    gemm_tf32<<<dim3(DD / 128, BT / 128), 256>>>(y_ptr, Wproj, bproj, out, BT, DD, DD);
}